// round 13
// baseline (speedup 1.0000x reference)
#include <cuda_runtime.h>
#include <math.h>
#include <stdint.h>

#define F    1024
#define NJ   64
#define C    256
#define HID  1024
#define H    8
#define D    128
#define M_TOT (NJ * F)      // 65536
#define EPSV 1e-6f

// Scratch (device globals — no allocation allowed in kernel_launch)
__device__ float g_Q[(size_t)M_TOT * HID];      // tf32-rounded, feature-mapped
__device__ float g_K[(size_t)M_TOT * HID];      // tf32-rounded, feature-mapped
__device__ float g_V[(size_t)M_TOT * HID];      // tf32-rounded
__device__ float g_KV[(size_t)NJ * H * D * D];  // [n,h,m,d], tf32-rounded
__device__ float g_Ksum[(size_t)NJ * H * D];
__device__ float g_Xr[(size_t)M_TOT * C];       // x as [m][k], tf32-rounded
__device__ float g_Wt[(size_t)3 * HID * C];     // W as [w][n][k], tf32-rounded

__device__ __forceinline__ float ftf32(float x) {
    float r;
    asm("cvt.rna.tf32.f32 %0, %1;" : "=f"(r) : "f"(x));
    return r;
}

__device__ __forceinline__ uint32_t smem_u32(const void* p) {
    uint32_t a;
    asm("{ .reg .u64 t; cvta.to.shared.u64 t, %1; cvt.u32.u64 %0, t; }"
        : "=r"(a) : "l"(p));
    return a;
}

__device__ __forceinline__ void cp16(uint32_t dst_smem, const void* src) {
    asm volatile("cp.async.cg.shared.global [%0], [%1], 16;"
                 :: "r"(dst_smem), "l"(__cvta_generic_to_global(src)) : "memory");
}
__device__ __forceinline__ void cp_commit() {
    asm volatile("cp.async.commit_group;" ::: "memory");
}
template <int N>
__device__ __forceinline__ void cp_wait() {
    asm volatile("cp.async.wait_group %0;" :: "n"(N) : "memory");
}

__device__ __forceinline__ void mma_tf32(float* c, const uint32_t* a,
                                         uint32_t b0, uint32_t b1) {
    asm volatile(
        "mma.sync.aligned.m16n8k8.row.col.f32.tf32.tf32.f32 "
        "{%0,%1,%2,%3}, {%4,%5,%6,%7}, {%8,%9}, {%0,%1,%2,%3};"
        : "+f"(c[0]), "+f"(c[1]), "+f"(c[2]), "+f"(c[3])
        : "r"(a[0]), "r"(a[1]), "r"(a[2]), "r"(a[3]), "r"(b0), "r"(b1));
}

__device__ __forceinline__ void ldsm4(uint32_t& r0, uint32_t& r1,
                                      uint32_t& r2, uint32_t& r3, uint32_t addr) {
    asm volatile("ldmatrix.sync.aligned.m8n8.x4.shared.b16 {%0,%1,%2,%3}, [%4];"
                 : "=r"(r0), "=r"(r1), "=r"(r2), "=r"(r3) : "r"(addr));
}

// ---------------------------------------------------------------------------
// Prep A: x[f][n][c] -> g_Xr[m][k] (m = n*F+f), tf32-rounded.
// ---------------------------------------------------------------------------
__global__ __launch_bounds__(256) void xr_kernel(const float* __restrict__ x)
{
    const int warp = threadIdx.x >> 5, lane = threadIdx.x & 31;
    const int m = blockIdx.x * 8 + warp;
    const int f = m & (F - 1), n = m >> 10;
    const float* src = x + ((size_t)f * NJ + n) * C + lane * 8;
    float* dst = g_Xr + (size_t)m * C + lane * 8;
    float4 v0 = *(const float4*)(src);
    float4 v1 = *(const float4*)(src + 4);
    v0.x = ftf32(v0.x); v0.y = ftf32(v0.y); v0.z = ftf32(v0.z); v0.w = ftf32(v0.w);
    v1.x = ftf32(v1.x); v1.y = ftf32(v1.y); v1.z = ftf32(v1.z); v1.w = ftf32(v1.w);
    *(float4*)(dst)     = v0;
    *(float4*)(dst + 4) = v1;
}

// ---------------------------------------------------------------------------
// Prep B: W[k][n] -> g_Wt[w][n][k], tf32-rounded (32x32 smem transpose).
// ---------------------------------------------------------------------------
__global__ __launch_bounds__(256) void wt_kernel(
    const float* __restrict__ Wq, const float* __restrict__ Wk,
    const float* __restrict__ Wv)
{
    __shared__ float t[32][33];
    const int w = blockIdx.z;
    const float* W = (w == 0) ? Wq : ((w == 1) ? Wk : Wv);
    const int k0 = blockIdx.x * 32, n0 = blockIdx.y * 32;
    const int lane = threadIdx.x & 31, warp = threadIdx.x >> 5;
#pragma unroll
    for (int i = 0; i < 4; i++) {
        const int ky = warp + i * 8;
        t[ky][lane] = ftf32(W[(size_t)(k0 + ky) * HID + n0 + lane]);
    }
    __syncthreads();
#pragma unroll
    for (int i = 0; i < 4; i++) {
        const int nr = warp * 4 + i;
        g_Wt[((size_t)w * HID + n0 + nr) * C + k0 + lane] = t[lane][nr];
    }
}

// ---------------------------------------------------------------------------
// Kernel 1: QKV projection (R12, proven). 512 threads, 128x256, 3-stage.
// ---------------------------------------------------------------------------
#define STAGE_BYTES 49152
__global__ __launch_bounds__(512) void qkv_mma_kernel(
    const float* __restrict__ bq, const float* __restrict__ bk,
    const float* __restrict__ bv)
{
    extern __shared__ float smem[];
    const uint32_t s0 = smem_u32(smem);

    const int tid  = threadIdx.x;
    const int lane = tid & 31;
    const int warp = tid >> 5;
    const int wm   = warp & 3;
    const int wn   = warp >> 2;
    const int gr   = lane >> 2;
    const int gc   = lane & 3;

    const int by = blockIdx.x;      // 0..11
    const int bm = blockIdx.y;      // 0..511
    const int w  = by >> 2;
    const int colbase = (by & 3) * 256;

    const int unit = lane >> 3;
    const int u2   = unit >> 1;
    const int urow = ((unit & 1) << 3) | (lane & 7);
    const uint32_t uoff = (uint32_t)urow * 128;
    const int rp = lane & 7;

    const float* aSrc = g_Xr + (size_t)(bm * 128) * C;
    const float* bSrc = g_Wt + ((size_t)w * HID + colbase) * C;
    int asrco[2]; uint32_t adsto[2];
#pragma unroll
    for (int i = 0; i < 2; i++) {
        const int c = i * 512 + tid, row = c >> 3, g = c & 7;   // 1024 chunks ✓
        asrco[i] = row * C + g * 4;
        adsto[i] = (uint32_t)(row * 128 + ((g ^ (row & 7)) << 4));
    }
    int bsrco[4]; uint32_t bdsto[4];
#pragma unroll
    for (int i = 0; i < 4; i++) {
        const int c = i * 512 + tid, row = c >> 3, g = c & 7;   // 2048 chunks ✓
        bsrco[i] = row * C + g * 4;
        bdsto[i] = (uint32_t)(16384 + row * 128 + ((g ^ (row & 7)) << 4));
    }

    float acc[2][8][4];
#pragma unroll
    for (int mf = 0; mf < 2; mf++)
#pragma unroll
        for (int nf = 0; nf < 8; nf++)
#pragma unroll
            for (int i = 0; i < 4; i++) acc[mf][nf][i] = 0.f;

#define ISSUE_STAGE(kt)                                                       \
    {                                                                         \
        const uint32_t sb = s0 + ((kt) % 3) * STAGE_BYTES;                    \
        const int kf = (kt) * 32;                                             \
        _Pragma("unroll")                                                     \
        for (int i = 0; i < 2; i++) cp16(sb + adsto[i], aSrc + kf + asrco[i]);\
        _Pragma("unroll")                                                     \
        for (int i = 0; i < 4; i++) cp16(sb + bdsto[i], bSrc + kf + bsrco[i]);\
    }

    ISSUE_STAGE(0) cp_commit();
    ISSUE_STAGE(1) cp_commit();

    for (int kt = 0; kt < 8; kt++) {
        cp_wait<1>();
        __syncthreads();
        if (kt + 2 < 8) ISSUE_STAGE(kt + 2)
        cp_commit();

        const uint32_t sA  = s0 + (kt % 3) * STAGE_BYTES;
        const uint32_t sBv = sA + 16384;
#pragma unroll
        for (int ks = 0; ks < 4; ks++) {
            const uint32_t kswz = (uint32_t)((((ks * 2 + u2) ^ rp) & 7) << 4);
            uint32_t afr[2][4];
#pragma unroll
            for (int mf = 0; mf < 2; mf++)
                ldsm4(afr[mf][0], afr[mf][1], afr[mf][2], afr[mf][3],
                      sA + (uint32_t)(wm * 4096 + mf * 2048) + uoff + kswz);
            uint32_t b0v[8], b1v[8];
#pragma unroll
            for (int nfp = 0; nfp < 4; nfp++)
                ldsm4(b0v[2 * nfp], b0v[2 * nfp + 1], b1v[2 * nfp], b1v[2 * nfp + 1],
                      sBv + (uint32_t)(wn * 8192 + nfp * 2048) + uoff + kswz);
#pragma unroll
            for (int nf = 0; nf < 8; nf++)
#pragma unroll
                for (int mf = 0; mf < 2; mf++)
                    mma_tf32(acc[mf][nf], afr[mf], b0v[nf], b1v[nf]);
        }
    }

    const float* bias = (w == 0) ? bq : ((w == 1) ? bk : bv);
    float* OUT        = (w == 0) ? g_Q : ((w == 1) ? g_K : g_V);
    const bool fmap = (w < 2);
#pragma unroll
    for (int mf = 0; mf < 2; mf++) {
        const int mrow = bm * 128 + wm * 32 + mf * 16 + gr;
#pragma unroll
        for (int nf = 0; nf < 8; nf++) {
            const int col = colbase + wn * 64 + nf * 8 + 2 * gc;
            const float b0v = bias[col];
            const float b1v = bias[col + 1];
            float v0 = acc[mf][nf][0] + b0v;
            float v1 = acc[mf][nf][1] + b1v;
            float v2 = acc[mf][nf][2] + b0v;
            float v3 = acc[mf][nf][3] + b1v;
            if (fmap) {
                v0 = (v0 > 0.f) ? (v0 + 1.f) : __expf(v0);
                v1 = (v1 > 0.f) ? (v1 + 1.f) : __expf(v1);
                v2 = (v2 > 0.f) ? (v2 + 1.f) : __expf(v2);
                v3 = (v3 > 0.f) ? (v3 + 1.f) : __expf(v3);
            }
            v0 = ftf32(v0); v1 = ftf32(v1); v2 = ftf32(v2); v3 = ftf32(v3);
            *(float2*)&OUT[(size_t)mrow * HID + col]       = make_float2(v0, v1);
            *(float2*)&OUT[(size_t)(mrow + 8) * HID + col] = make_float2(v2, v3);
        }
    }
}

// ===================== kv kernel: 3-stage cp.async pipeline ==================
// Chunk math: each tile per matrix = 32 x 128 fl = 16KB = 1024 chunks
//             = 4/thread x 256 thr.
#define MMA_TILE_BODY(As, Bs, acc)                                            \
    _Pragma("unroll")                                                         \
    for (int ks = 0; ks < 4; ks++) {                                          \
        const int kk = ks * 8;                                                \
        uint32_t afr[2][4];                                                   \
        _Pragma("unroll")                                                     \
        for (int mf = 0; mf < 2; mf++) {                                      \
            const int m0 = wm2 * 32 + mf * 16;                                \
            afr[mf][0] = __float_as_uint(As[kk + gc][m0 + gr]);               \
            afr[mf][1] = __float_as_uint(As[kk + gc][m0 + gr + 8]);           \
            afr[mf][2] = __float_as_uint(As[kk + gc + 4][m0 + gr]);           \
            afr[mf][3] = __float_as_uint(As[kk + gc + 4][m0 + gr + 8]);       \
        }                                                                     \
        _Pragma("unroll")                                                     \
        for (int nf = 0; nf < 8; nf++) {                                      \
            const int n0 = wn2 * 64 + nf * 8;                                 \
            const uint32_t b0 = __float_as_uint(Bs[kk + gc][n0 + gr]);        \
            const uint32_t b1 = __float_as_uint(Bs[kk + gc + 4][n0 + gr]);    \
            mma_tf32(acc[0][nf], afr[0], b0, b1);                             \
            mma_tf32(acc[1][nf], afr[1], b0, b1);                             \
        }                                                                     \
    }

#define KV_TILE_FL (32 * 136)
__global__ __launch_bounds__(256) void kv_mma_kernel()
{
    extern __shared__ float kvsm[];
    float (*As3)[32][136] = (float(*)[32][136])kvsm;                  // V [st][s][m]
    float (*Bs3)[32][136] = (float(*)[32][136])(kvsm + 3 * KV_TILE_FL); // K [st][s][d]
    __shared__ float sKsum[128];

    const int tid  = threadIdx.x;
    const int lane = tid & 31;
    const int warp = tid >> 5;
    const int wm2  = warp & 3;
    const int wn2  = warp >> 2;
    const int gr   = lane >> 2;
    const int gc   = lane & 3;

    const int n = blockIdx.x, h = blockIdx.y;
    const size_t base = (size_t)n * F * HID + (size_t)h * D;

    // 4 chunks/thread: c = i*256+tid -> row = c>>5 (0..31), granule = c&31
    int crow[4], cg4[4];
    uint32_t adst[3][4], bdst[3][4];
#pragma unroll
    for (int i = 0; i < 4; i++) {
        const int c = i * 256 + tid;
        crow[i] = c >> 5;
        cg4[i]  = (c & 31) * 4;
#pragma unroll
        for (int st = 0; st < 3; st++) {
            adst[st][i] = smem_u32(&As3[st][crow[i]][cg4[i]]);
            bdst[st][i] = smem_u32(&Bs3[st][crow[i]][cg4[i]]);
        }
    }

    if (tid < 128) sKsum[tid] = 0.f;
    float4 kacc[4];
#pragma unroll
    for (int i = 0; i < 4; i++) kacc[i] = make_float4(0.f, 0.f, 0.f, 0.f);

    float acc[2][8][4];
#pragma unroll
    for (int mf = 0; mf < 2; mf++)
#pragma unroll
        for (int nf = 0; nf < 8; nf++)
#pragma unroll
            for (int i = 0; i < 4; i++) acc[mf][nf][i] = 0.f;

#define KV_ISSUE(t)                                                           \
    {                                                                         \
        const int _st = (t) % 3;                                              \
        _Pragma("unroll")                                                     \
        for (int i = 0; i < 4; i++) {                                         \
            const size_t so = base + (size_t)((t) * 32 + crow[i]) * HID + cg4[i]; \
            cp16(adst[_st][i], g_V + so);                                     \
            cp16(bdst[_st][i], g_K + so);                                     \
        }                                                                     \
    }

    KV_ISSUE(0) cp_commit();
    KV_ISSUE(1) cp_commit();

    for (int t = 0; t < 32; t++) {
        cp_wait<1>();
        __syncthreads();
        if (t + 2 < 32) KV_ISSUE(t + 2)
        cp_commit();

        const int st = t % 3;
#pragma unroll
        for (int i = 0; i < 4; i++) {
            float4 kb = *(const float4*)&Bs3[st][crow[i]][cg4[i]];
            kacc[i].x += kb.x; kacc[i].y += kb.y; kacc[i].z += kb.z; kacc[i].w += kb.w;
        }

        MMA_TILE_BODY(As3[st], Bs3[st], acc)
    }

#pragma unroll
    for (int i = 0; i < 4; i++) {
        atomicAdd(&sKsum[cg4[i] + 0], kacc[i].x);
        atomicAdd(&sKsum[cg4[i] + 1], kacc[i].y);
        atomicAdd(&sKsum[cg4[i] + 2], kacc[i].z);
        atomicAdd(&sKsum[cg4[i] + 3], kacc[i].w);
    }
    __syncthreads();

    const size_t nh = (size_t)n * H + h;
    if (tid < 128) g_Ksum[nh * D + tid] = sKsum[tid];

    const size_t kvbase = nh * D * D;
#pragma unroll
    for (int mf = 0; mf < 2; mf++) {
        const int mrow = wm2 * 32 + mf * 16 + gr;
#pragma unroll
        for (int nf = 0; nf < 8; nf++) {
            const int ncol = wn2 * 64 + nf * 8 + 2 * gc;
            *(float2*)&g_KV[kvbase + (size_t)mrow * D + ncol] =
                make_float2(ftf32(acc[mf][nf][0]), ftf32(acc[mf][nf][1]));
            *(float2*)&g_KV[kvbase + (size_t)(mrow + 8) * D + ncol] =
                make_float2(ftf32(acc[mf][nf][2]), ftf32(acc[mf][nf][3]));
        }
    }
}

// ---------------------------------------------------------------------------
// Kernel 3: out = Z * (Q @ KV^T). 512 threads, block 256(l) x 128(m), K=128.
// 16 warps (4l x 4m), warp tile 64x32. 3-stage cp.async + ldmatrix.
// Chunk math/stage: A 256x32 fl = 2048 chunks = 4/thr x 512 ✓;
//                   B 128x32 fl = 1024 chunks = 2/thr x 512 ✓.
// ---------------------------------------------------------------------------
#define OSTAGE 49152
__global__ __launch_bounds__(512) void out_mma_kernel(float* __restrict__ out)
{
    extern __shared__ float osm[];
    __shared__ float sZ[256];
    const uint32_t s0 = smem_u32(osm);

    const int tid  = threadIdx.x;
    const int lane = tid & 31;
    const int warp = tid >> 5;
    const int wm   = warp & 3;      // l offset wm*64
    const int wn   = warp >> 2;     // m offset wn*32
    const int gr   = lane >> 2;
    const int gc   = lane & 3;

    const int lt = blockIdx.x;      // 0..3 (256 l-rows each)
    const int n = blockIdx.y, h = blockIdx.z;
    const int l0 = lt * 256;
    const size_t nh = (size_t)n * H + h;
    const size_t qbase  = ((size_t)n * F + l0) * HID + (size_t)h * D;
    const size_t kvbase = nh * (size_t)D * D;

    const int unit = lane >> 3;
    const int u2   = unit >> 1;
    const int urow = ((unit & 1) << 3) | (lane & 7);
    const uint32_t uoff = (uint32_t)urow * 128;
    const int rp = lane & 7;

    const float* aSrc = g_Q + qbase;
    const float* bSrc = g_KV + kvbase;
    int asrco[4]; uint32_t adsto[4];
#pragma unroll
    for (int i = 0; i < 4; i++) {
        const int c = i * 512 + tid, row = c >> 3, g = c & 7;   // 256 rows
        asrco[i] = row * HID + g * 4;
        adsto[i] = (uint32_t)(row * 128 + ((g ^ (row & 7)) << 4));
    }
    int bsrco[2]; uint32_t bdsto[2];
#pragma unroll
    for (int i = 0; i < 2; i++) {
        const int c = i * 512 + tid, row = c >> 3, g = c & 7;   // 128 rows
        bsrco[i] = row * D + g * 4;
        bdsto[i] = (uint32_t)(32768 + row * 128 + ((g ^ (row & 7)) << 4));
    }

#define O_ISSUE(kt)                                                           \
    {                                                                         \
        const uint32_t sb = s0 + ((kt) % 3) * OSTAGE;                         \
        const int kf = (kt) * 32;                                             \
        _Pragma("unroll")                                                     \
        for (int i = 0; i < 4; i++) cp16(sb + adsto[i], aSrc + kf + asrco[i]);\
        _Pragma("unroll")                                                     \
        for (int i = 0; i < 2; i++) cp16(sb + bdsto[i], bSrc + kf + bsrco[i]);\
    }

    O_ISSUE(0) cp_commit();
    O_ISSUE(1) cp_commit();

    // Z while copies fly: 16 warps x 16 rows = 256 rows
    {
        float4 kv4 = *(const float4*)(g_Ksum + nh * D + lane * 4);
#pragma unroll
        for (int r8 = 0; r8 < 16; r8++) {
            const int row = warp * 16 + r8;
            const float* q = g_Q + qbase + (size_t)row * HID;
            float4 qv = *(const float4*)(q + lane * 4);
            float dd = qv.x * kv4.x + qv.y * kv4.y + qv.z * kv4.z + qv.w * kv4.w;
#pragma unroll
            for (int off = 16; off; off >>= 1) dd += __shfl_xor_sync(0xffffffffu, dd, off);
            if (lane == 0) sZ[row] = 1.f / (dd + EPSV);
        }
    }

    float acc[4][4][4];
#pragma unroll
    for (int mf = 0; mf < 4; mf++)
#pragma unroll
        for (int nf = 0; nf < 4; nf++)
#pragma unroll
            for (int i = 0; i < 4; i++) acc[mf][nf][i] = 0.f;

    for (int kt = 0; kt < 4; kt++) {
        cp_wait<1>();
        __syncthreads();
        if (kt + 2 < 4) O_ISSUE(kt + 2)
        cp_commit();

        const uint32_t sA  = s0 + (kt % 3) * OSTAGE;
        const uint32_t sBv = sA + 32768;
#pragma unroll
        for (int ks = 0; ks < 4; ks++) {
            const uint32_t kswz = (uint32_t)((((ks * 2 + u2) ^ rp) & 7) << 4);
            uint32_t afr[4][4];
#pragma unroll
            for (int mf = 0; mf < 4; mf++)
                ldsm4(afr[mf][0], afr[mf][1], afr[mf][2], afr[mf][3],
                      sA + (uint32_t)(wm * 8192 + mf * 2048) + uoff + kswz);
            uint32_t b0v[4], b1v[4];
#pragma unroll
            for (int nfp = 0; nfp < 2; nfp++)
                ldsm4(b0v[2 * nfp], b0v[2 * nfp + 1], b1v[2 * nfp], b1v[2 * nfp + 1],
                      sBv + (uint32_t)(wn * 4096 + nfp * 2048) + uoff + kswz);
#pragma unroll
            for (int nf = 0; nf < 4; nf++)
#pragma unroll
                for (int mf = 0; mf < 4; mf++)
                    mma_tf32(acc[mf][nf], afr[mf], b0v[nf], b1v[nf]);
        }
    }

#pragma unroll
    for (int mf = 0; mf < 4; mf++) {
        const int row = wm * 64 + mf * 16 + gr;        // l within tile (0..255)
        const float z0 = sZ[row];
        const float z1 = sZ[row + 8];
        const size_t ob0 = (size_t)(l0 + row) * (NJ * HID) + (size_t)n * HID + (size_t)h * D;
        const size_t ob1 = (size_t)(l0 + row + 8) * (NJ * HID) + (size_t)n * HID + (size_t)h * D;
#pragma unroll
        for (int nf = 0; nf < 4; nf++) {
            const int ncol = wn * 32 + nf * 8 + 2 * gc;
            *(float2*)&out[ob0 + ncol] =
                make_float2(acc[mf][nf][0] * z0, acc[mf][nf][1] * z0);
            *(float2*)&out[ob1 + ncol] =
                make_float2(acc[mf][nf][2] * z1, acc[mf][nf][3] * z1);
        }
    }
}

// ---------------------------------------------------------------------------
extern "C" void kernel_launch(void* const* d_in, const int* in_sizes, int n_in,
                              void* d_out, int out_size)
{
    const float* x  = (const float*)d_in[0];
    const float* Wq = (const float*)d_in[1];
    const float* bq = (const float*)d_in[2];
    const float* Wk = (const float*)d_in[3];
    const float* bk = (const float*)d_in[4];
    const float* Wv = (const float*)d_in[5];
    const float* bv = (const float*)d_in[6];
    float* out = (float*)d_out;

    xr_kernel<<<M_TOT / 8, 256>>>(x);
    dim3 gw(C / 32, HID / 32, 3);
    wt_kernel<<<gw, 256>>>(Wq, Wk, Wv);

    const int smem1 = 3 * STAGE_BYTES;   // 147456 B
    cudaFuncSetAttribute(qkv_mma_kernel,
                         cudaFuncAttributeMaxDynamicSharedMemorySize, smem1);
    dim3 g1(12, M_TOT / 128);
    qkv_mma_kernel<<<g1, 512, smem1>>>(bq, bk, bv);

    const int smem2 = 6 * KV_TILE_FL * 4;   // 104448 B
    cudaFuncSetAttribute(kv_mma_kernel,
                         cudaFuncAttributeMaxDynamicSharedMemorySize, smem2);
    dim3 g2(NJ, H);
    kv_mma_kernel<<<g2, 256, smem2>>>();

    const int smem3 = 3 * OSTAGE;        // 147456 B
    cudaFuncSetAttribute(out_mma_kernel,
                         cudaFuncAttributeMaxDynamicSharedMemorySize, smem3);
    dim3 g3(F / 256, NJ, H);
    out_mma_kernel<<<g3, 512, smem3>>>(out);
}

// round 15
// speedup vs baseline: 1.0361x; 1.0361x over previous
#include <cuda_runtime.h>
#include <math.h>
#include <stdint.h>

#define F    1024
#define NJ   64
#define C    256
#define HID  1024
#define H    8
#define D    128
#define M_TOT (NJ * F)      // 65536
#define EPSV 1e-6f

// Scratch (device globals — no allocation allowed in kernel_launch)
__device__ float g_Q[(size_t)M_TOT * HID];      // tf32-rounded, feature-mapped
__device__ float g_K[(size_t)M_TOT * HID];      // tf32-rounded, feature-mapped
__device__ float g_V[(size_t)M_TOT * HID];      // tf32-rounded
__device__ float g_KV[(size_t)NJ * H * D * D];  // [n,h,m,d], tf32-rounded
__device__ float g_Ksum[(size_t)NJ * H * D];
__device__ float g_Xr[(size_t)M_TOT * C];       // x as [m][k], tf32-rounded
__device__ float g_Wt[(size_t)3 * HID * C];     // W as [w][n][k], tf32-rounded

__device__ __forceinline__ float ftf32(float x) {
    float r;
    asm("cvt.rna.tf32.f32 %0, %1;" : "=f"(r) : "f"(x));
    return r;
}

__device__ __forceinline__ uint32_t smem_u32(const void* p) {
    uint32_t a;
    asm("{ .reg .u64 t; cvta.to.shared.u64 t, %1; cvt.u32.u64 %0, t; }"
        : "=r"(a) : "l"(p));
    return a;
}

__device__ __forceinline__ void cp16(uint32_t dst_smem, const void* src) {
    asm volatile("cp.async.cg.shared.global [%0], [%1], 16;"
                 :: "r"(dst_smem), "l"(__cvta_generic_to_global(src)) : "memory");
}
__device__ __forceinline__ void cp_commit() {
    asm volatile("cp.async.commit_group;" ::: "memory");
}
template <int N>
__device__ __forceinline__ void cp_wait() {
    asm volatile("cp.async.wait_group %0;" :: "n"(N) : "memory");
}

__device__ __forceinline__ void mma_tf32(float* c, const uint32_t* a,
                                         uint32_t b0, uint32_t b1) {
    asm volatile(
        "mma.sync.aligned.m16n8k8.row.col.f32.tf32.tf32.f32 "
        "{%0,%1,%2,%3}, {%4,%5,%6,%7}, {%8,%9}, {%0,%1,%2,%3};"
        : "+f"(c[0]), "+f"(c[1]), "+f"(c[2]), "+f"(c[3])
        : "r"(a[0]), "r"(a[1]), "r"(a[2]), "r"(a[3]), "r"(b0), "r"(b1));
}

__device__ __forceinline__ void ldsm4(uint32_t& r0, uint32_t& r1,
                                      uint32_t& r2, uint32_t& r3, uint32_t addr) {
    asm volatile("ldmatrix.sync.aligned.m8n8.x4.shared.b16 {%0,%1,%2,%3}, [%4];"
                 : "=r"(r0), "=r"(r1), "=r"(r2), "=r"(r3) : "r"(addr));
}

// ---------------------------------------------------------------------------
// Prep A: x[f][n][c] -> g_Xr[m][k] (m = n*F+f), tf32-rounded.
// ---------------------------------------------------------------------------
__global__ __launch_bounds__(256) void xr_kernel(const float* __restrict__ x)
{
    const int warp = threadIdx.x >> 5, lane = threadIdx.x & 31;
    const int m = blockIdx.x * 8 + warp;
    const int f = m & (F - 1), n = m >> 10;
    const float* src = x + ((size_t)f * NJ + n) * C + lane * 8;
    float* dst = g_Xr + (size_t)m * C + lane * 8;
    float4 v0 = *(const float4*)(src);
    float4 v1 = *(const float4*)(src + 4);
    v0.x = ftf32(v0.x); v0.y = ftf32(v0.y); v0.z = ftf32(v0.z); v0.w = ftf32(v0.w);
    v1.x = ftf32(v1.x); v1.y = ftf32(v1.y); v1.z = ftf32(v1.z); v1.w = ftf32(v1.w);
    *(float4*)(dst)     = v0;
    *(float4*)(dst + 4) = v1;
}

// ---------------------------------------------------------------------------
// Prep B: W[k][n] -> g_Wt[w][n][k], tf32-rounded (32x32 smem transpose).
// ---------------------------------------------------------------------------
__global__ __launch_bounds__(256) void wt_kernel(
    const float* __restrict__ Wq, const float* __restrict__ Wk,
    const float* __restrict__ Wv)
{
    __shared__ float t[32][33];
    const int w = blockIdx.z;
    const float* W = (w == 0) ? Wq : ((w == 1) ? Wk : Wv);
    const int k0 = blockIdx.x * 32, n0 = blockIdx.y * 32;
    const int lane = threadIdx.x & 31, warp = threadIdx.x >> 5;
#pragma unroll
    for (int i = 0; i < 4; i++) {
        const int ky = warp + i * 8;
        t[ky][lane] = ftf32(W[(size_t)(k0 + ky) * HID + n0 + lane]);
    }
    __syncthreads();
#pragma unroll
    for (int i = 0; i < 4; i++) {
        const int nr = warp * 4 + i;
        g_Wt[((size_t)w * HID + n0 + nr) * C + k0 + lane] = t[lane][nr];
    }
}

// ---------------------------------------------------------------------------
// Kernel 1: QKV projection (R12, proven). 512 threads, 128x256, 3-stage.
// ---------------------------------------------------------------------------
#define STAGE_BYTES 49152
__global__ __launch_bounds__(512) void qkv_mma_kernel(
    const float* __restrict__ bq, const float* __restrict__ bk,
    const float* __restrict__ bv)
{
    extern __shared__ float smem[];
    const uint32_t s0 = smem_u32(smem);

    const int tid  = threadIdx.x;
    const int lane = tid & 31;
    const int warp = tid >> 5;
    const int wm   = warp & 3;
    const int wn   = warp >> 2;
    const int gr   = lane >> 2;
    const int gc   = lane & 3;

    const int by = blockIdx.x;      // 0..11
    const int bm = blockIdx.y;      // 0..511
    const int w  = by >> 2;
    const int colbase = (by & 3) * 256;

    const int unit = lane >> 3;
    const int u2   = unit >> 1;
    const int urow = ((unit & 1) << 3) | (lane & 7);
    const uint32_t uoff = (uint32_t)urow * 128;
    const int rp = lane & 7;

    const float* aSrc = g_Xr + (size_t)(bm * 128) * C;
    const float* bSrc = g_Wt + ((size_t)w * HID + colbase) * C;
    int asrco[2]; uint32_t adsto[2];
#pragma unroll
    for (int i = 0; i < 2; i++) {
        const int c = i * 512 + tid, row = c >> 3, g = c & 7;   // 1024 chunks ✓
        asrco[i] = row * C + g * 4;
        adsto[i] = (uint32_t)(row * 128 + ((g ^ (row & 7)) << 4));
    }
    int bsrco[4]; uint32_t bdsto[4];
#pragma unroll
    for (int i = 0; i < 4; i++) {
        const int c = i * 512 + tid, row = c >> 3, g = c & 7;   // 2048 chunks ✓
        bsrco[i] = row * C + g * 4;
        bdsto[i] = (uint32_t)(16384 + row * 128 + ((g ^ (row & 7)) << 4));
    }

    float acc[2][8][4];
#pragma unroll
    for (int mf = 0; mf < 2; mf++)
#pragma unroll
        for (int nf = 0; nf < 8; nf++)
#pragma unroll
            for (int i = 0; i < 4; i++) acc[mf][nf][i] = 0.f;

#define ISSUE_STAGE(kt)                                                       \
    {                                                                         \
        const uint32_t sb = s0 + ((kt) % 3) * STAGE_BYTES;                    \
        const int kf = (kt) * 32;                                             \
        _Pragma("unroll")                                                     \
        for (int i = 0; i < 2; i++) cp16(sb + adsto[i], aSrc + kf + asrco[i]);\
        _Pragma("unroll")                                                     \
        for (int i = 0; i < 4; i++) cp16(sb + bdsto[i], bSrc + kf + bsrco[i]);\
    }

    ISSUE_STAGE(0) cp_commit();
    ISSUE_STAGE(1) cp_commit();

    for (int kt = 0; kt < 8; kt++) {
        cp_wait<1>();
        __syncthreads();
        if (kt + 2 < 8) ISSUE_STAGE(kt + 2)
        cp_commit();

        const uint32_t sA  = s0 + (kt % 3) * STAGE_BYTES;
        const uint32_t sBv = sA + 16384;
#pragma unroll
        for (int ks = 0; ks < 4; ks++) {
            const uint32_t kswz = (uint32_t)((((ks * 2 + u2) ^ rp) & 7) << 4);
            uint32_t afr[2][4];
#pragma unroll
            for (int mf = 0; mf < 2; mf++)
                ldsm4(afr[mf][0], afr[mf][1], afr[mf][2], afr[mf][3],
                      sA + (uint32_t)(wm * 4096 + mf * 2048) + uoff + kswz);
            uint32_t b0v[8], b1v[8];
#pragma unroll
            for (int nfp = 0; nfp < 4; nfp++)
                ldsm4(b0v[2 * nfp], b0v[2 * nfp + 1], b1v[2 * nfp], b1v[2 * nfp + 1],
                      sBv + (uint32_t)(wn * 8192 + nfp * 2048) + uoff + kswz);
#pragma unroll
            for (int nf = 0; nf < 8; nf++)
#pragma unroll
                for (int mf = 0; mf < 2; mf++)
                    mma_tf32(acc[mf][nf], afr[mf], b0v[nf], b1v[nf]);
        }
    }

    const float* bias = (w == 0) ? bq : ((w == 1) ? bk : bv);
    float* OUT        = (w == 0) ? g_Q : ((w == 1) ? g_K : g_V);
    const bool fmap = (w < 2);
#pragma unroll
    for (int mf = 0; mf < 2; mf++) {
        const int mrow = bm * 128 + wm * 32 + mf * 16 + gr;
#pragma unroll
        for (int nf = 0; nf < 8; nf++) {
            const int col = colbase + wn * 64 + nf * 8 + 2 * gc;
            const float b0v = bias[col];
            const float b1v = bias[col + 1];
            float v0 = acc[mf][nf][0] + b0v;
            float v1 = acc[mf][nf][1] + b1v;
            float v2 = acc[mf][nf][2] + b0v;
            float v3 = acc[mf][nf][3] + b1v;
            if (fmap) {
                v0 = (v0 > 0.f) ? (v0 + 1.f) : __expf(v0);
                v1 = (v1 > 0.f) ? (v1 + 1.f) : __expf(v1);
                v2 = (v2 > 0.f) ? (v2 + 1.f) : __expf(v2);
                v3 = (v3 > 0.f) ? (v3 + 1.f) : __expf(v3);
            }
            v0 = ftf32(v0); v1 = ftf32(v1); v2 = ftf32(v2); v3 = ftf32(v3);
            *(float2*)&OUT[(size_t)mrow * HID + col]       = make_float2(v0, v1);
            *(float2*)&OUT[(size_t)(mrow + 8) * HID + col] = make_float2(v2, v3);
        }
    }
}

// ===================== kv kernel: 3-stage cp.async (R13, proven) =============
// Chunk math: tile/matrix = 32 x 128 fl = 16KB = 1024 chunks = 4/thr x 256 ✓.
#define MMA_TILE_BODY(As, Bs, acc)                                            \
    _Pragma("unroll")                                                         \
    for (int ks = 0; ks < 4; ks++) {                                          \
        const int kk = ks * 8;                                                \
        uint32_t afr[2][4];                                                   \
        _Pragma("unroll")                                                     \
        for (int mf = 0; mf < 2; mf++) {                                      \
            const int m0 = wm2 * 32 + mf * 16;                                \
            afr[mf][0] = __float_as_uint(As[kk + gc][m0 + gr]);               \
            afr[mf][1] = __float_as_uint(As[kk + gc][m0 + gr + 8]);           \
            afr[mf][2] = __float_as_uint(As[kk + gc + 4][m0 + gr]);           \
            afr[mf][3] = __float_as_uint(As[kk + gc + 4][m0 + gr + 8]);       \
        }                                                                     \
        _Pragma("unroll")                                                     \
        for (int nf = 0; nf < 8; nf++) {                                      \
            const int n0 = wn2 * 64 + nf * 8;                                 \
            const uint32_t b0 = __float_as_uint(Bs[kk + gc][n0 + gr]);        \
            const uint32_t b1 = __float_as_uint(Bs[kk + gc + 4][n0 + gr]);    \
            mma_tf32(acc[0][nf], afr[0], b0, b1);                             \
            mma_tf32(acc[1][nf], afr[1], b0, b1);                             \
        }                                                                     \
    }

#define KV_TILE_FL (32 * 136)
__global__ __launch_bounds__(256) void kv_mma_kernel()
{
    extern __shared__ float kvsm[];
    float (*As3)[32][136] = (float(*)[32][136])kvsm;                    // V [st][s][m]
    float (*Bs3)[32][136] = (float(*)[32][136])(kvsm + 3 * KV_TILE_FL); // K [st][s][d]
    __shared__ float sKsum[128];

    const int tid  = threadIdx.x;
    const int lane = tid & 31;
    const int warp = tid >> 5;
    const int wm2  = warp & 3;
    const int wn2  = warp >> 2;
    const int gr   = lane >> 2;
    const int gc   = lane & 3;

    const int n = blockIdx.x, h = blockIdx.y;
    const size_t base = (size_t)n * F * HID + (size_t)h * D;

    int crow[4], cg4[4];
    uint32_t adst[3][4], bdst[3][4];
#pragma unroll
    for (int i = 0; i < 4; i++) {
        const int c = i * 256 + tid;
        crow[i] = c >> 5;
        cg4[i]  = (c & 31) * 4;
#pragma unroll
        for (int st = 0; st < 3; st++) {
            adst[st][i] = smem_u32(&As3[st][crow[i]][cg4[i]]);
            bdst[st][i] = smem_u32(&Bs3[st][crow[i]][cg4[i]]);
        }
    }

    if (tid < 128) sKsum[tid] = 0.f;
    float4 kacc[4];
#pragma unroll
    for (int i = 0; i < 4; i++) kacc[i] = make_float4(0.f, 0.f, 0.f, 0.f);

    float acc[2][8][4];
#pragma unroll
    for (int mf = 0; mf < 2; mf++)
#pragma unroll
        for (int nf = 0; nf < 8; nf++)
#pragma unroll
            for (int i = 0; i < 4; i++) acc[mf][nf][i] = 0.f;

#define KV_ISSUE(t)                                                           \
    {                                                                         \
        const int _st = (t) % 3;                                              \
        _Pragma("unroll")                                                     \
        for (int i = 0; i < 4; i++) {                                         \
            const size_t so = base + (size_t)((t) * 32 + crow[i]) * HID + cg4[i]; \
            cp16(adst[_st][i], g_V + so);                                     \
            cp16(bdst[_st][i], g_K + so);                                     \
        }                                                                     \
    }

    KV_ISSUE(0) cp_commit();
    KV_ISSUE(1) cp_commit();

    for (int t = 0; t < 32; t++) {
        cp_wait<1>();
        __syncthreads();
        if (t + 2 < 32) KV_ISSUE(t + 2)
        cp_commit();

        const int st = t % 3;
#pragma unroll
        for (int i = 0; i < 4; i++) {
            float4 kb = *(const float4*)&Bs3[st][crow[i]][cg4[i]];
            kacc[i].x += kb.x; kacc[i].y += kb.y; kacc[i].z += kb.z; kacc[i].w += kb.w;
        }

        MMA_TILE_BODY(As3[st], Bs3[st], acc)
    }

#pragma unroll
    for (int i = 0; i < 4; i++) {
        atomicAdd(&sKsum[cg4[i] + 0], kacc[i].x);
        atomicAdd(&sKsum[cg4[i] + 1], kacc[i].y);
        atomicAdd(&sKsum[cg4[i] + 2], kacc[i].z);
        atomicAdd(&sKsum[cg4[i] + 3], kacc[i].w);
    }
    __syncthreads();

    const size_t nh = (size_t)n * H + h;
    if (tid < 128) g_Ksum[nh * D + tid] = sKsum[tid];

    const size_t kvbase = nh * D * D;
#pragma unroll
    for (int mf = 0; mf < 2; mf++) {
        const int mrow = wm2 * 32 + mf * 16 + gr;
#pragma unroll
        for (int nf = 0; nf < 8; nf++) {
            const int ncol = wn2 * 64 + nf * 8 + 2 * gc;
            *(float2*)&g_KV[kvbase + (size_t)mrow * D + ncol] =
                make_float2(ftf32(acc[mf][nf][0]), ftf32(acc[mf][nf][1]));
            *(float2*)&g_KV[kvbase + (size_t)(mrow + 8) * D + ncol] =
                make_float2(ftf32(acc[mf][nf][2]), ftf32(acc[mf][nf][3]));
        }
    }
}

// ---------------------------------------------------------------------------
// Kernel 3: out = Z * (Q @ KV^T). R12 structure, 2-stage (64KB smem ->
// 3 CTAs/SM). Block 128x128, 256 thr, warp tile 64x32, K=128 (4 tiles).
// Chunk math: A,B tiles each 128x32 fl = 16KB = 1024 chunks = 4/thr x 256 ✓.
// ---------------------------------------------------------------------------
#define OSTAGE 32768
__global__ __launch_bounds__(256) void out_mma_kernel(float* __restrict__ out)
{
    extern __shared__ float osm[];
    __shared__ float sZ[128];
    const uint32_t s0 = smem_u32(osm);

    const int tid  = threadIdx.x;
    const int lane = tid & 31;
    const int warp = tid >> 5;
    const int wm   = warp & 1;
    const int wn   = warp >> 1;
    const int gr   = lane >> 2;
    const int gc   = lane & 3;

    const int lt = blockIdx.x;
    const int n = blockIdx.y, h = blockIdx.z;
    const int l0 = lt * 128;
    const size_t nh = (size_t)n * H + h;
    const size_t qbase  = ((size_t)n * F + l0) * HID + (size_t)h * D;
    const size_t kvbase = nh * (size_t)D * D;

    const int unit = lane >> 3;
    const int u2   = unit >> 1;
    const int urow = ((unit & 1) << 3) | (lane & 7);
    const uint32_t uoff = (uint32_t)urow * 128;
    const int rp = lane & 7;

    const float* aSrc = g_Q + qbase;
    const float* bSrc = g_KV + kvbase;
    int asrco[4]; int bsrco[4]; uint32_t adsto[4], bdsto[4];
#pragma unroll
    for (int i = 0; i < 4; i++) {
        const int c = i * 256 + tid, row = c >> 3, g = c & 7;
        asrco[i] = row * HID + g * 4;
        bsrco[i] = row * D + g * 4;
        adsto[i] = (uint32_t)(row * 128 + ((g ^ (row & 7)) << 4));
        bdsto[i] = (uint32_t)(16384 + row * 128 + ((g ^ (row & 7)) << 4));
    }

#define O_ISSUE(kt)                                                           \
    {                                                                         \
        const uint32_t sb = s0 + ((kt) & 1) * OSTAGE;                         \
        const int kf = (kt) * 32;                                             \
        _Pragma("unroll")                                                     \
        for (int i = 0; i < 4; i++) {                                         \
            cp16(sb + adsto[i], aSrc + kf + asrco[i]);                        \
            cp16(sb + bdsto[i], bSrc + kf + bsrco[i]);                        \
        }                                                                     \
    }

    O_ISSUE(0) cp_commit();

    // Z while the first copy flies
    {
        float4 kv4 = *(const float4*)(g_Ksum + nh * D + lane * 4);
#pragma unroll
        for (int r8 = 0; r8 < 16; r8++) {
            const int row = warp * 16 + r8;
            const float* q = g_Q + qbase + (size_t)row * HID;
            float4 qv = *(const float4*)(q + lane * 4);
            float dd = qv.x * kv4.x + qv.y * kv4.y + qv.z * kv4.z + qv.w * kv4.w;
#pragma unroll
            for (int off = 16; off; off >>= 1) dd += __shfl_xor_sync(0xffffffffu, dd, off);
            if (lane == 0) sZ[row] = 1.f / (dd + EPSV);
        }
    }

    float acc[4][4][4];
#pragma unroll
    for (int mf = 0; mf < 4; mf++)
#pragma unroll
        for (int nf = 0; nf < 4; nf++)
#pragma unroll
            for (int i = 0; i < 4; i++) acc[mf][nf][i] = 0.f;

    for (int kt = 0; kt < 4; kt++) {
        __syncthreads();             // compute(kt-1) done; buffer (kt+1)&1 free
        if (kt < 3) { O_ISSUE(kt + 1) cp_commit(); cp_wait<1>(); }
        else cp_wait<0>();
        __syncthreads();             // publish stage kt

        const uint32_t sA  = s0 + (kt & 1) * OSTAGE;
        const uint32_t sBv = sA + 16384;
#pragma unroll
        for (int ks = 0; ks < 4; ks++) {
            const uint32_t kswz = (uint32_t)((((ks * 2 + u2) ^ rp) & 7) << 4);
            uint32_t afr[4][4];
#pragma unroll
            for (int mf = 0; mf < 4; mf++)
                ldsm4(afr[mf][0], afr[mf][1], afr[mf][2], afr[mf][3],
                      sA + (uint32_t)(wm * 8192 + mf * 2048) + uoff + kswz);
            uint32_t b0v[4], b1v[4];
#pragma unroll
            for (int nfp = 0; nfp < 2; nfp++)
                ldsm4(b0v[2 * nfp], b0v[2 * nfp + 1], b1v[2 * nfp], b1v[2 * nfp + 1],
                      sBv + (uint32_t)(wn * 4096 + nfp * 2048) + uoff + kswz);
#pragma unroll
            for (int nf = 0; nf < 4; nf++)
#pragma unroll
                for (int mf = 0; mf < 4; mf++)
                    mma_tf32(acc[mf][nf], afr[mf], b0v[nf], b1v[nf]);
        }
    }

#pragma unroll
    for (int mf = 0; mf < 4; mf++) {
        const int row = wm * 64 + mf * 16 + gr;
        const float z0 = sZ[row];
        const float z1 = sZ[row + 8];
        const size_t ob0 = (size_t)(l0 + row) * (NJ * HID) + (size_t)n * HID + (size_t)h * D;
        const size_t ob1 = (size_t)(l0 + row + 8) * (NJ * HID) + (size_t)n * HID + (size_t)h * D;
#pragma unroll
        for (int nf = 0; nf < 4; nf++) {
            const int ncol = wn * 32 + nf * 8 + 2 * gc;
            *(float2*)&out[ob0 + ncol] =
                make_float2(acc[mf][nf][0] * z0, acc[mf][nf][1] * z0);
            *(float2*)&out[ob1 + ncol] =
                make_float2(acc[mf][nf][2] * z1, acc[mf][nf][3] * z1);
        }
    }
}

// ---------------------------------------------------------------------------
extern "C" void kernel_launch(void* const* d_in, const int* in_sizes, int n_in,
                              void* d_out, int out_size)
{
    const float* x  = (const float*)d_in[0];
    const float* Wq = (const float*)d_in[1];
    const float* bq = (const float*)d_in[2];
    const float* Wk = (const float*)d_in[3];
    const float* bk = (const float*)d_in[4];
    const float* Wv = (const float*)d_in[5];
    const float* bv = (const float*)d_in[6];
    float* out = (float*)d_out;

    xr_kernel<<<M_TOT / 8, 256>>>(x);
    dim3 gw(C / 32, HID / 32, 3);
    wt_kernel<<<gw, 256>>>(Wq, Wk, Wv);

    const int smem1 = 3 * STAGE_BYTES;   // 147456 B
    cudaFuncSetAttribute(qkv_mma_kernel,
                         cudaFuncAttributeMaxDynamicSharedMemorySize, smem1);
    dim3 g1(12, M_TOT / 128);
    qkv_mma_kernel<<<g1, 512, smem1>>>(bq, bk, bv);

    const int smem2 = 6 * KV_TILE_FL * 4;   // 104448 B
    cudaFuncSetAttribute(kv_mma_kernel,
                         cudaFuncAttributeMaxDynamicSharedMemorySize, smem2);
    dim3 g2(NJ, H);
    kv_mma_kernel<<<g2, 256, smem2>>>();

    const int smem3 = 2 * OSTAGE;        // 65536 B -> 3 CTAs/SM
    cudaFuncSetAttribute(out_mma_kernel,
                         cudaFuncAttributeMaxDynamicSharedMemorySize, smem3);
    dim3 g3(F / 128, NJ, H);
    out_mma_kernel<<<g3, 256, smem3>>>(out);
}

// round 16
// speedup vs baseline: 1.0428x; 1.0064x over previous
#include <cuda_runtime.h>
#include <math.h>
#include <stdint.h>

#define F    1024
#define NJ   64
#define C    256
#define HID  1024
#define H    8
#define D    128
#define M_TOT (NJ * F)      // 65536
#define EPSV 1e-6f

// Scratch (device globals — no allocation allowed in kernel_launch)
__device__ float g_Q[(size_t)M_TOT * HID];      // tf32-rounded, feature-mapped
__device__ float g_K[(size_t)M_TOT * HID];      // tf32-rounded, feature-mapped
__device__ float g_V[(size_t)M_TOT * HID];      // tf32-rounded
__device__ float g_KV[(size_t)NJ * H * D * D];  // [n,h,m,d], tf32-rounded
__device__ float g_Ksum[(size_t)NJ * H * D];
__device__ float g_Xr[(size_t)M_TOT * C];       // x as [m][k], tf32-rounded
__device__ float g_Wt[(size_t)3 * HID * C];     // W as [w][n][k], tf32-rounded

__device__ __forceinline__ float ftf32(float x) {
    float r;
    asm("cvt.rna.tf32.f32 %0, %1;" : "=f"(r) : "f"(x));
    return r;
}

__device__ __forceinline__ uint32_t smem_u32(const void* p) {
    uint32_t a;
    asm("{ .reg .u64 t; cvta.to.shared.u64 t, %1; cvt.u32.u64 %0, t; }"
        : "=r"(a) : "l"(p));
    return a;
}

__device__ __forceinline__ void cp16(uint32_t dst_smem, const void* src) {
    asm volatile("cp.async.cg.shared.global [%0], [%1], 16;"
                 :: "r"(dst_smem), "l"(__cvta_generic_to_global(src)) : "memory");
}
__device__ __forceinline__ void cp_commit() {
    asm volatile("cp.async.commit_group;" ::: "memory");
}
template <int N>
__device__ __forceinline__ void cp_wait() {
    asm volatile("cp.async.wait_group %0;" :: "n"(N) : "memory");
}

__device__ __forceinline__ void mma_tf32(float* c, const uint32_t* a,
                                         uint32_t b0, uint32_t b1) {
    asm volatile(
        "mma.sync.aligned.m16n8k8.row.col.f32.tf32.tf32.f32 "
        "{%0,%1,%2,%3}, {%4,%5,%6,%7}, {%8,%9}, {%0,%1,%2,%3};"
        : "+f"(c[0]), "+f"(c[1]), "+f"(c[2]), "+f"(c[3])
        : "r"(a[0]), "r"(a[1]), "r"(a[2]), "r"(a[3]), "r"(b0), "r"(b1));
}

__device__ __forceinline__ void ldsm4(uint32_t& r0, uint32_t& r1,
                                      uint32_t& r2, uint32_t& r3, uint32_t addr) {
    asm volatile("ldmatrix.sync.aligned.m8n8.x4.shared.b16 {%0,%1,%2,%3}, [%4];"
                 : "=r"(r0), "=r"(r1), "=r"(r2), "=r"(r3) : "r"(addr));
}

// ---------------------------------------------------------------------------
// Prep A: x[f][n][c] -> g_Xr[m][k] (m = n*F+f), tf32-rounded.
// ---------------------------------------------------------------------------
__global__ __launch_bounds__(256) void xr_kernel(const float* __restrict__ x)
{
    const int warp = threadIdx.x >> 5, lane = threadIdx.x & 31;
    const int m = blockIdx.x * 8 + warp;
    const int f = m & (F - 1), n = m >> 10;
    const float* src = x + ((size_t)f * NJ + n) * C + lane * 8;
    float* dst = g_Xr + (size_t)m * C + lane * 8;
    float4 v0 = *(const float4*)(src);
    float4 v1 = *(const float4*)(src + 4);
    v0.x = ftf32(v0.x); v0.y = ftf32(v0.y); v0.z = ftf32(v0.z); v0.w = ftf32(v0.w);
    v1.x = ftf32(v1.x); v1.y = ftf32(v1.y); v1.z = ftf32(v1.z); v1.w = ftf32(v1.w);
    *(float4*)(dst)     = v0;
    *(float4*)(dst + 4) = v1;
}

// ---------------------------------------------------------------------------
// Prep B: W[k][n] -> g_Wt[w][n][k], tf32-rounded (32x32 smem transpose).
// ---------------------------------------------------------------------------
__global__ __launch_bounds__(256) void wt_kernel(
    const float* __restrict__ Wq, const float* __restrict__ Wk,
    const float* __restrict__ Wv)
{
    __shared__ float t[32][33];
    const int w = blockIdx.z;
    const float* W = (w == 0) ? Wq : ((w == 1) ? Wk : Wv);
    const int k0 = blockIdx.x * 32, n0 = blockIdx.y * 32;
    const int lane = threadIdx.x & 31, warp = threadIdx.x >> 5;
#pragma unroll
    for (int i = 0; i < 4; i++) {
        const int ky = warp + i * 8;
        t[ky][lane] = ftf32(W[(size_t)(k0 + ky) * HID + n0 + lane]);
    }
    __syncthreads();
#pragma unroll
    for (int i = 0; i < 4; i++) {
        const int nr = warp * 4 + i;
        g_Wt[((size_t)w * HID + n0 + nr) * C + k0 + lane] = t[lane][nr];
    }
}

// ---------------------------------------------------------------------------
// Kernel 1: QKV projection. 512 threads (16 warps, 4m x 4n), warp tile 32x64.
// Block 128(M)x256(N), BK=64, 2-stage cp.async + ldmatrix. Rows = 256B,
// swizzle within 8-granule halves: swz(g,row) = ((g&8)<<4)|(((g^row)&7)<<4).
// Chunk math/stage: A 128x64 fl = 32KB = 2048 chunks = 4/thr x 512 ✓
//                   B 256x64 fl = 64KB = 4096 chunks = 8/thr x 512 ✓
// ---------------------------------------------------------------------------
#define STAGE_BYTES 98304
__global__ __launch_bounds__(512) void qkv_mma_kernel(
    const float* __restrict__ bq, const float* __restrict__ bk,
    const float* __restrict__ bv)
{
    extern __shared__ float smem[];
    const uint32_t s0 = smem_u32(smem);

    const int tid  = threadIdx.x;
    const int lane = tid & 31;
    const int warp = tid >> 5;
    const int wm   = warp & 3;      // m offset wm*32
    const int wn   = warp >> 2;     // n offset wn*64
    const int gr   = lane >> 2;
    const int gc   = lane & 3;

    const int by = blockIdx.x;      // 0..11
    const int bm = blockIdx.y;      // 0..511
    const int w  = by >> 2;
    const int colbase = (by & 3) * 256;

    const int unit = lane >> 3;
    const int u2   = unit >> 1;
    const int urow = ((unit & 1) << 3) | (lane & 7);
    const uint32_t uoff = (uint32_t)urow * 256;
    const int rp = lane & 7;

    const float* aSrc = g_Xr + (size_t)(bm * 128) * C;
    const float* bSrc = g_Wt + ((size_t)w * HID + colbase) * C;
    int asrco[4]; uint32_t adsto[4];
#pragma unroll
    for (int i = 0; i < 4; i++) {
        const int c = i * 512 + tid, row = c >> 4, g = c & 15;   // 128 rows x 16 gran
        asrco[i] = row * C + g * 4;
        adsto[i] = (uint32_t)(row * 256 + ((g & 8) << 4) + ((((g ^ row) & 7)) << 4));
    }
    int bsrco[8]; uint32_t bdsto[8];
#pragma unroll
    for (int i = 0; i < 8; i++) {
        const int c = i * 512 + tid, row = c >> 4, g = c & 15;   // 256 rows x 16 gran
        bsrco[i] = row * C + g * 4;
        bdsto[i] = (uint32_t)(32768 + row * 256 + ((g & 8) << 4) + ((((g ^ row) & 7)) << 4));
    }

    float acc[2][8][4];
#pragma unroll
    for (int mf = 0; mf < 2; mf++)
#pragma unroll
        for (int nf = 0; nf < 8; nf++)
#pragma unroll
            for (int i = 0; i < 4; i++) acc[mf][nf][i] = 0.f;

#define ISSUE_STAGE(kt)                                                       \
    {                                                                         \
        const uint32_t sb = s0 + ((kt) & 1) * STAGE_BYTES;                    \
        const int kf = (kt) * 64;                                             \
        _Pragma("unroll")                                                     \
        for (int i = 0; i < 4; i++) cp16(sb + adsto[i], aSrc + kf + asrco[i]);\
        _Pragma("unroll")                                                     \
        for (int i = 0; i < 8; i++) cp16(sb + bdsto[i], bSrc + kf + bsrco[i]);\
    }

    ISSUE_STAGE(0) cp_commit();

    for (int kt = 0; kt < 4; kt++) {
        __syncthreads();             // compute(kt-1) done; buffer (kt+1)&1 free
        if (kt < 3) { ISSUE_STAGE(kt + 1) cp_commit(); cp_wait<1>(); }
        else cp_wait<0>();
        __syncthreads();             // publish stage kt

        const uint32_t sA  = s0 + (kt & 1) * STAGE_BYTES;
        const uint32_t sBv = sA + 32768;
#pragma unroll
        for (int ks = 0; ks < 8; ks++) {
            const int ksel = ks * 2 + u2;           // granule 0..15
            const uint32_t kswz = (uint32_t)(((ksel & 8) << 4) +
                                             ((((ksel ^ rp) & 7)) << 4));
            uint32_t afr[2][4];
#pragma unroll
            for (int mf = 0; mf < 2; mf++)
                ldsm4(afr[mf][0], afr[mf][1], afr[mf][2], afr[mf][3],
                      sA + (uint32_t)(wm * 8192 + mf * 4096) + uoff + kswz);
            uint32_t b0v[8], b1v[8];
#pragma unroll
            for (int nfp = 0; nfp < 4; nfp++)
                ldsm4(b0v[2 * nfp], b0v[2 * nfp + 1], b1v[2 * nfp], b1v[2 * nfp + 1],
                      sBv + (uint32_t)(wn * 16384 + nfp * 4096) + uoff + kswz);
#pragma unroll
            for (int nf = 0; nf < 8; nf++)
#pragma unroll
                for (int mf = 0; mf < 2; mf++)
                    mma_tf32(acc[mf][nf], afr[mf], b0v[nf], b1v[nf]);
        }
    }

    const float* bias = (w == 0) ? bq : ((w == 1) ? bk : bv);
    float* OUT        = (w == 0) ? g_Q : ((w == 1) ? g_K : g_V);
    const bool fmap = (w < 2);
#pragma unroll
    for (int mf = 0; mf < 2; mf++) {
        const int mrow = bm * 128 + wm * 32 + mf * 16 + gr;
#pragma unroll
        for (int nf = 0; nf < 8; nf++) {
            const int col = colbase + wn * 64 + nf * 8 + 2 * gc;
            const float b0v = bias[col];
            const float b1v = bias[col + 1];
            float v0 = acc[mf][nf][0] + b0v;
            float v1 = acc[mf][nf][1] + b1v;
            float v2 = acc[mf][nf][2] + b0v;
            float v3 = acc[mf][nf][3] + b1v;
            if (fmap) {
                v0 = (v0 > 0.f) ? (v0 + 1.f) : __expf(v0);
                v1 = (v1 > 0.f) ? (v1 + 1.f) : __expf(v1);
                v2 = (v2 > 0.f) ? (v2 + 1.f) : __expf(v2);
                v3 = (v3 > 0.f) ? (v3 + 1.f) : __expf(v3);
            }
            v0 = ftf32(v0); v1 = ftf32(v1); v2 = ftf32(v2); v3 = ftf32(v3);
            *(float2*)&OUT[(size_t)mrow * HID + col]       = make_float2(v0, v1);
            *(float2*)&OUT[(size_t)(mrow + 8) * HID + col] = make_float2(v2, v3);
        }
    }
}

// ===================== kv kernel: 3-stage cp.async (R13, proven) =============
#define MMA_TILE_BODY(As, Bs, acc)                                            \
    _Pragma("unroll")                                                         \
    for (int ks = 0; ks < 4; ks++) {                                          \
        const int kk = ks * 8;                                                \
        uint32_t afr[2][4];                                                   \
        _Pragma("unroll")                                                     \
        for (int mf = 0; mf < 2; mf++) {                                      \
            const int m0 = wm2 * 32 + mf * 16;                                \
            afr[mf][0] = __float_as_uint(As[kk + gc][m0 + gr]);               \
            afr[mf][1] = __float_as_uint(As[kk + gc][m0 + gr + 8]);           \
            afr[mf][2] = __float_as_uint(As[kk + gc + 4][m0 + gr]);           \
            afr[mf][3] = __float_as_uint(As[kk + gc + 4][m0 + gr + 8]);       \
        }                                                                     \
        _Pragma("unroll")                                                     \
        for (int nf = 0; nf < 8; nf++) {                                      \
            const int n0 = wn2 * 64 + nf * 8;                                 \
            const uint32_t b0 = __float_as_uint(Bs[kk + gc][n0 + gr]);        \
            const uint32_t b1 = __float_as_uint(Bs[kk + gc + 4][n0 + gr]);    \
            mma_tf32(acc[0][nf], afr[0], b0, b1);                             \
            mma_tf32(acc[1][nf], afr[1], b0, b1);                             \
        }                                                                     \
    }

#define KV_TILE_FL (32 * 136)
__global__ __launch_bounds__(256) void kv_mma_kernel()
{
    extern __shared__ float kvsm[];
    float (*As3)[32][136] = (float(*)[32][136])kvsm;
    float (*Bs3)[32][136] = (float(*)[32][136])(kvsm + 3 * KV_TILE_FL);
    __shared__ float sKsum[128];

    const int tid  = threadIdx.x;
    const int lane = tid & 31;
    const int warp = tid >> 5;
    const int wm2  = warp & 3;
    const int wn2  = warp >> 2;
    const int gr   = lane >> 2;
    const int gc   = lane & 3;

    const int n = blockIdx.x, h = blockIdx.y;
    const size_t base = (size_t)n * F * HID + (size_t)h * D;

    int crow[4], cg4[4];
    uint32_t adst[3][4], bdst[3][4];
#pragma unroll
    for (int i = 0; i < 4; i++) {
        const int c = i * 256 + tid;
        crow[i] = c >> 5;
        cg4[i]  = (c & 31) * 4;
#pragma unroll
        for (int st = 0; st < 3; st++) {
            adst[st][i] = smem_u32(&As3[st][crow[i]][cg4[i]]);
            bdst[st][i] = smem_u32(&Bs3[st][crow[i]][cg4[i]]);
        }
    }

    if (tid < 128) sKsum[tid] = 0.f;
    float4 kacc[4];
#pragma unroll
    for (int i = 0; i < 4; i++) kacc[i] = make_float4(0.f, 0.f, 0.f, 0.f);

    float acc[2][8][4];
#pragma unroll
    for (int mf = 0; mf < 2; mf++)
#pragma unroll
        for (int nf = 0; nf < 8; nf++)
#pragma unroll
            for (int i = 0; i < 4; i++) acc[mf][nf][i] = 0.f;

#define KV_ISSUE(t)                                                           \
    {                                                                         \
        const int _st = (t) % 3;                                              \
        _Pragma("unroll")                                                     \
        for (int i = 0; i < 4; i++) {                                         \
            const size_t so = base + (size_t)((t) * 32 + crow[i]) * HID + cg4[i]; \
            cp16(adst[_st][i], g_V + so);                                     \
            cp16(bdst[_st][i], g_K + so);                                     \
        }                                                                     \
    }

    KV_ISSUE(0) cp_commit();
    KV_ISSUE(1) cp_commit();

    for (int t = 0; t < 32; t++) {
        cp_wait<1>();
        __syncthreads();
        if (t + 2 < 32) KV_ISSUE(t + 2)
        cp_commit();

        const int st = t % 3;
#pragma unroll
        for (int i = 0; i < 4; i++) {
            float4 kb = *(const float4*)&Bs3[st][crow[i]][cg4[i]];
            kacc[i].x += kb.x; kacc[i].y += kb.y; kacc[i].z += kb.z; kacc[i].w += kb.w;
        }

        MMA_TILE_BODY(As3[st], Bs3[st], acc)
    }

#pragma unroll
    for (int i = 0; i < 4; i++) {
        atomicAdd(&sKsum[cg4[i] + 0], kacc[i].x);
        atomicAdd(&sKsum[cg4[i] + 1], kacc[i].y);
        atomicAdd(&sKsum[cg4[i] + 2], kacc[i].z);
        atomicAdd(&sKsum[cg4[i] + 3], kacc[i].w);
    }
    __syncthreads();

    const size_t nh = (size_t)n * H + h;
    if (tid < 128) g_Ksum[nh * D + tid] = sKsum[tid];

    const size_t kvbase = nh * D * D;
#pragma unroll
    for (int mf = 0; mf < 2; mf++) {
        const int mrow = wm2 * 32 + mf * 16 + gr;
#pragma unroll
        for (int nf = 0; nf < 8; nf++) {
            const int ncol = wn2 * 64 + nf * 8 + 2 * gc;
            *(float2*)&g_KV[kvbase + (size_t)mrow * D + ncol] =
                make_float2(ftf32(acc[mf][nf][0]), ftf32(acc[mf][nf][1]));
            *(float2*)&g_KV[kvbase + (size_t)(mrow + 8) * D + ncol] =
                make_float2(ftf32(acc[mf][nf][2]), ftf32(acc[mf][nf][3]));
        }
    }
}

// ---------------------------------------------------------------------------
// Kernel 3: out = Z * (Q @ KV^T). R15 proven: 2-stage, 64KB, 3 CTAs/SM.
// ---------------------------------------------------------------------------
#define OSTAGE 32768
__global__ __launch_bounds__(256) void out_mma_kernel(float* __restrict__ out)
{
    extern __shared__ float osm[];
    __shared__ float sZ[128];
    const uint32_t s0 = smem_u32(osm);

    const int tid  = threadIdx.x;
    const int lane = tid & 31;
    const int warp = tid >> 5;
    const int wm   = warp & 1;
    const int wn   = warp >> 1;
    const int gr   = lane >> 2;
    const int gc   = lane & 3;

    const int lt = blockIdx.x;
    const int n = blockIdx.y, h = blockIdx.z;
    const int l0 = lt * 128;
    const size_t nh = (size_t)n * H + h;
    const size_t qbase  = ((size_t)n * F + l0) * HID + (size_t)h * D;
    const size_t kvbase = nh * (size_t)D * D;

    const int unit = lane >> 3;
    const int u2   = unit >> 1;
    const int urow = ((unit & 1) << 3) | (lane & 7);
    const uint32_t uoff = (uint32_t)urow * 128;
    const int rp = lane & 7;

    const float* aSrc = g_Q + qbase;
    const float* bSrc = g_KV + kvbase;
    int asrco[4]; int bsrco[4]; uint32_t adsto[4], bdsto[4];
#pragma unroll
    for (int i = 0; i < 4; i++) {
        const int c = i * 256 + tid, row = c >> 3, g = c & 7;
        asrco[i] = row * HID + g * 4;
        bsrco[i] = row * D + g * 4;
        adsto[i] = (uint32_t)(row * 128 + ((g ^ (row & 7)) << 4));
        bdsto[i] = (uint32_t)(16384 + row * 128 + ((g ^ (row & 7)) << 4));
    }

#define O_ISSUE(kt)                                                           \
    {                                                                         \
        const uint32_t sb = s0 + ((kt) & 1) * OSTAGE;                         \
        const int kf = (kt) * 32;                                             \
        _Pragma("unroll")                                                     \
        for (int i = 0; i < 4; i++) {                                         \
            cp16(sb + adsto[i], aSrc + kf + asrco[i]);                        \
            cp16(sb + bdsto[i], bSrc + kf + bsrco[i]);                        \
        }                                                                     \
    }

    O_ISSUE(0) cp_commit();

    {
        float4 kv4 = *(const float4*)(g_Ksum + nh * D + lane * 4);
#pragma unroll
        for (int r8 = 0; r8 < 16; r8++) {
            const int row = warp * 16 + r8;
            const float* q = g_Q + qbase + (size_t)row * HID;
            float4 qv = *(const float4*)(q + lane * 4);
            float dd = qv.x * kv4.x + qv.y * kv4.y + qv.z * kv4.z + qv.w * kv4.w;
#pragma unroll
            for (int off = 16; off; off >>= 1) dd += __shfl_xor_sync(0xffffffffu, dd, off);
            if (lane == 0) sZ[row] = 1.f / (dd + EPSV);
        }
    }

    float acc[4][4][4];
#pragma unroll
    for (int mf = 0; mf < 4; mf++)
#pragma unroll
        for (int nf = 0; nf < 4; nf++)
#pragma unroll
            for (int i = 0; i < 4; i++) acc[mf][nf][i] = 0.f;

    for (int kt = 0; kt < 4; kt++) {
        __syncthreads();
        if (kt < 3) { O_ISSUE(kt + 1) cp_commit(); cp_wait<1>(); }
        else cp_wait<0>();
        __syncthreads();

        const uint32_t sA  = s0 + (kt & 1) * OSTAGE;
        const uint32_t sBv = sA + 16384;
#pragma unroll
        for (int ks = 0; ks < 4; ks++) {
            const uint32_t kswz = (uint32_t)((((ks * 2 + u2) ^ rp) & 7) << 4);
            uint32_t afr[4][4];
#pragma unroll
            for (int mf = 0; mf < 4; mf++)
                ldsm4(afr[mf][0], afr[mf][1], afr[mf][2], afr[mf][3],
                      sA + (uint32_t)(wm * 8192 + mf * 2048) + uoff + kswz);
            uint32_t b0v[4], b1v[4];
#pragma unroll
            for (int nfp = 0; nfp < 2; nfp++)
                ldsm4(b0v[2 * nfp], b0v[2 * nfp + 1], b1v[2 * nfp], b1v[2 * nfp + 1],
                      sBv + (uint32_t)(wn * 4096 + nfp * 2048) + uoff + kswz);
#pragma unroll
            for (int nf = 0; nf < 4; nf++)
#pragma unroll
                for (int mf = 0; mf < 4; mf++)
                    mma_tf32(acc[mf][nf], afr[mf], b0v[nf], b1v[nf]);
        }
    }

#pragma unroll
    for (int mf = 0; mf < 4; mf++) {
        const int row = wm * 64 + mf * 16 + gr;
        const float z0 = sZ[row];
        const float z1 = sZ[row + 8];
        const size_t ob0 = (size_t)(l0 + row) * (NJ * HID) + (size_t)n * HID + (size_t)h * D;
        const size_t ob1 = (size_t)(l0 + row + 8) * (NJ * HID) + (size_t)n * HID + (size_t)h * D;
#pragma unroll
        for (int nf = 0; nf < 4; nf++) {
            const int ncol = wn * 32 + nf * 8 + 2 * gc;
            *(float2*)&out[ob0 + ncol] =
                make_float2(acc[mf][nf][0] * z0, acc[mf][nf][1] * z0);
            *(float2*)&out[ob1 + ncol] =
                make_float2(acc[mf][nf][2] * z1, acc[mf][nf][3] * z1);
        }
    }
}

// ---------------------------------------------------------------------------
extern "C" void kernel_launch(void* const* d_in, const int* in_sizes, int n_in,
                              void* d_out, int out_size)
{
    const float* x  = (const float*)d_in[0];
    const float* Wq = (const float*)d_in[1];
    const float* bq = (const float*)d_in[2];
    const float* Wk = (const float*)d_in[3];
    const float* bk = (const float*)d_in[4];
    const float* Wv = (const float*)d_in[5];
    const float* bv = (const float*)d_in[6];
    float* out = (float*)d_out;

    xr_kernel<<<M_TOT / 8, 256>>>(x);
    dim3 gw(C / 32, HID / 32, 3);
    wt_kernel<<<gw, 256>>>(Wq, Wk, Wv);

    const int smem1 = 2 * STAGE_BYTES;   // 196608 B (BK=64, 2 stages)
    cudaFuncSetAttribute(qkv_mma_kernel,
                         cudaFuncAttributeMaxDynamicSharedMemorySize, smem1);
    dim3 g1(12, M_TOT / 128);
    qkv_mma_kernel<<<g1, 512, smem1>>>(bq, bk, bv);

    const int smem2 = 6 * KV_TILE_FL * 4;   // 104448 B
    cudaFuncSetAttribute(kv_mma_kernel,
                         cudaFuncAttributeMaxDynamicSharedMemorySize, smem2);
    dim3 g2(NJ, H);
    kv_mma_kernel<<<g2, 256, smem2>>>();

    const int smem3 = 2 * OSTAGE;        // 65536 B
    cudaFuncSetAttribute(out_mma_kernel,
                         cudaFuncAttributeMaxDynamicSharedMemorySize, smem3);
    dim3 g3(F / 128, NJ, H);
    out_mma_kernel<<<g3, 256, smem3>>>(out);
}